// round 15
// baseline (speedup 1.0000x reference)
#include <cuda_runtime.h>
#include <cuda_bf16.h>
#include <math.h>
#include <stdint.h>

// ---------------------------------------------------------------------------
// VAE_Gumbel: B=4096, D=5000, H=512, Z=64
// R15: mma.sync tf32 GEMMs restructured for HMMA issue density:
//   - 4 warps/CTA, 64x64 warp tiles (32 HMMA per kk vs 16)  -> 67% HMMA share
//   - B operand k-paired + swizzled (ld.shared.v2, conflict-free half-warps)
//   - cp.async for stage t+2 issued BEFORE compute of stage t (true overlap)
//   - all GEMM inputs pre-converted tf32; A k-paired (unchanged from R14)
// ---------------------------------------------------------------------------

#define Bsz 4096
#define Ddim 5000
#define Hdim 512
#define Zdim 64
#define KPAD_D 5024          // Ddim padded to 32
#define NPAD_D 5120          // Ddim padded to 128
#define DGRP 628             // KPAD_D / 8

// fp32 scratch
__device__ float g_h[Bsz * Hdim];          // h (pre-BN)
__device__ float g_w[(size_t)Bsz * Ddim];  // w (gumbel input)
__device__ float g_scale[Hdim];
__device__ float g_shift[Hdim];
__device__ float g_mlvb[128];              // packed mean|logvar bias

// tf32 (u32) scratch — zero-initialized at load; pads never written stay 0
__device__ uint32_t g_xt[(size_t)Bsz * KPAD_D];   // x,  k-paired (A fmt)
__device__ uint32_t g_xmt[(size_t)Bsz * KPAD_D];  // xm, k-paired (A fmt)
__device__ uint32_t g_hnt[Bsz * Hdim];            // hn, k-paired (A fmt)
__device__ uint32_t g_e1t[Bsz * 2 * Hdim];        // enc1 out / dec1 out
__device__ uint32_t g_e2t[Bsz * Hdim];
__device__ uint32_t g_e3t[Bsz * Hdim];
__device__ uint32_t g_e4t[Bsz * Hdim];
__device__ uint32_t g_zt[Bsz * Zdim];
// tf32 weights, B fmt: k-paired interleaved: word = pg*2*Npad + 2n + h
//   pg = (k>>3)*4 + (k&3), h = (k>>2)&1
__device__ uint32_t g_w1t[(size_t)KPAD_D * Hdim];
__device__ uint32_t g_w2t[(size_t)Hdim * NPAD_D];
__device__ uint32_t g_ew1t[(size_t)KPAD_D * 2 * Hdim];
__device__ uint32_t g_ew2t[2 * Hdim * Hdim];
__device__ uint32_t g_ew3t[Hdim * Hdim];
__device__ uint32_t g_ew4t[Hdim * Hdim];
__device__ uint32_t g_mlvt[Hdim * 128];
__device__ uint32_t g_dw1t[Zdim * 2 * Hdim];
__device__ uint32_t g_dw2t[(size_t)2 * Hdim * NPAD_D];

__device__ __forceinline__ unsigned tf32u(float x) {
    unsigned r;
    asm("cvt.rna.tf32.f32 %0, %1;" : "=r"(r) : "f"(x));
    return r;
}
__device__ __forceinline__ uint32_t smem_u32(const void* p) {
    uint32_t a;
    asm("{ .reg .u64 t; cvta.to.shared.u64 t, %1; cvt.u32.u64 %0, t; }"
        : "=r"(a) : "l"(p));
    return a;
}
// A-format k-pair permutation within groups of 8: (k,k+4) adjacent
__device__ __forceinline__ int permcol(int c) {
    return (c & ~7) | ((c & 3) * 2) | ((c >> 2) & 1);
}
__device__ __forceinline__ void cp_async16(uint32_t dst, const uint32_t* src) {
    asm volatile("cp.async.cg.shared.global [%0], [%1], 16;\n"
                 :: "r"(dst), "l"(src));
}

#define EPI_F32      0
#define EPI_F32_SIG  1
#define EPI_T32_LK   2
#define EPI_MEANLV   3

// ---------------------------------------------------------------------------
// tf32 mma.sync GEMM.
//  At: [M][Kpad] tf32, A k-paired per 8-group (slot s holds k=(s&1)*4+(s>>1)).
//  Bt: k-paired interleaved B fmt (see above).
//  CTA tile 128x128, BK=32, 3-stage cp.async, 128 threads = 4 warps (2m x 2n),
//  warp tile 64x64 (4 mt x 8 nn, 32 HMMA per kk).
//  Kpad % 32 == 0, Npad % 128 == 0, M % 128 == 0 guaranteed by caller.
// ---------------------------------------------------------------------------
#define A_STAGE   16384                 // 128 rows * 128B
#define B_STAGE   16384                 // 16 pair-rows * 1024B
#define STAGE_BYTES (A_STAGE + B_STAGE) // 32768
#define GEMM_SMEM  (3 * STAGE_BYTES)    // 98304

__device__ __forceinline__ void stage_load(
    uint32_t sb, const uint32_t* __restrict__ At, const uint32_t* __restrict__ Bt,
    int m0, int n0, int k0, int Kpad, int Npad, int tid)
{
    // A: thread -> row tid, 8 chunks of 16B, chunk-XOR swizzle
    const uint32_t* asrc = At + (size_t)(m0 + tid) * Kpad + k0;
    uint32_t adst = sb + tid * 128;
    const int asw = (tid & 3) << 1;
#pragma unroll
    for (int c = 0; c < 8; c++)
        cp_async16(adst + ((c ^ asw) << 4), asrc + c * 4);

    // B: thread -> pair-row pr = tid>>3, 8 chunks (cc, cc+8, ...), byte-XOR 32*(pr&3)
    const int pr = tid >> 3, cc = tid & 7;
    const uint32_t* bsrc = Bt + ((size_t)(k0 >> 1) + pr) * (2 * (size_t)Npad)
                              + 2 * n0 + cc * 4;
    const uint32_t bdst = sb + A_STAGE + pr * 1024;
    const uint32_t bsw = (pr & 3) * 32;
#pragma unroll
    for (int j = 0; j < 8; j++)
        cp_async16(bdst + (((cc * 16) + j * 128) ^ bsw), bsrc + j * 32);
}

template <int EPI>
__global__ __launch_bounds__(128, 2) void tc2_gemm(
    const uint32_t* __restrict__ At, const uint32_t* __restrict__ Bt,
    const float* __restrict__ bias,
    float* __restrict__ C0, float* __restrict__ C1, uint32_t* __restrict__ Ct,
    int M, int N, int Kpad, int Npad)
{
    extern __shared__ char smem[];
    const uint32_t sbase = smem_u32(smem);
    const int tid = threadIdx.x;
    const int lane = tid & 31;
    const int wid = tid >> 5;
    const int wm = (wid & 1) * 64;
    const int wn = (wid >> 1) * 64;
    const int m0 = blockIdx.y * 128;
    const int n0 = blockIdx.x * 128;

    float acc[4][8][4];
#pragma unroll
    for (int i = 0; i < 4; i++)
#pragma unroll
        for (int j = 0; j < 8; j++)
#pragma unroll
            for (int q = 0; q < 4; q++) acc[i][j][q] = 0.f;

    const int nt = Kpad >> 5;

#pragma unroll
    for (int t = 0; t < 2; t++) {
        if (t < nt) stage_load(sbase + t * STAGE_BYTES, At, Bt, m0, n0, t << 5, Kpad, Npad, tid);
        asm volatile("cp.async.commit_group;\n" ::: "memory");
    }

    const int ar = lane >> 2, q = lane & 3;

    for (int t = 0; t < nt; t++) {
        asm volatile("cp.async.wait_group 1;\n" ::: "memory");
        __syncthreads();

        // issue next-next stage loads BEFORE compute so they overlap it
        if (t + 2 < nt)
            stage_load(sbase + ((t + 2) % 3) * STAGE_BYTES, At, Bt, m0, n0,
                       (t + 2) << 5, Kpad, Npad, tid);
        asm volatile("cp.async.commit_group;\n" ::: "memory");

        const uint32_t as = sbase + (t % 3) * STAGE_BYTES;
        const uint32_t bs = as + A_STAGE;

#pragma unroll
        for (int kk = 0; kk < 4; kk++) {
            uint32_t a[4][4], b[8][2];
#pragma unroll
            for (int mt = 0; mt < 4; mt++) {
                int m = wm + mt * 16 + ar;
                uint32_t ad0 = as + m * 128 +
                    (((kk * 2 + (q >> 1)) ^ ((m & 3) << 1)) << 4) + (q & 1) * 8;
                asm("ld.shared.v2.u32 {%0,%1},[%2];"
                    : "=r"(a[mt][0]), "=r"(a[mt][2]) : "r"(ad0));
                int m1 = m + 8;
                uint32_t ad1 = as + m1 * 128 +
                    (((kk * 2 + (q >> 1)) ^ ((m1 & 3) << 1)) << 4) + (q & 1) * 8;
                asm("ld.shared.v2.u32 {%0,%1},[%2];"
                    : "=r"(a[mt][1]), "=r"(a[mt][3]) : "r"(ad1));
            }
            const uint32_t brow = bs + (kk * 4 + q) * 1024;
            const uint32_t bxor = q * 32;
#pragma unroll
            for (int nn = 0; nn < 8; nn++) {
                int n = wn + nn * 8 + ar;
                asm("ld.shared.v2.u32 {%0,%1},[%2];"
                    : "=r"(b[nn][0]), "=r"(b[nn][1])
                    : "r"(brow + ((uint32_t)(n * 8) ^ bxor)));
            }
#pragma unroll
            for (int mt = 0; mt < 4; mt++)
#pragma unroll
                for (int nn = 0; nn < 8; nn++)
                    asm volatile(
                        "mma.sync.aligned.m16n8k8.row.col.f32.tf32.tf32.f32 "
                        "{%0,%1,%2,%3},{%4,%5,%6,%7},{%8,%9},{%0,%1,%2,%3};\n"
                        : "+f"(acc[mt][nn][0]), "+f"(acc[mt][nn][1]),
                          "+f"(acc[mt][nn][2]), "+f"(acc[mt][nn][3])
                        : "r"(a[mt][0]), "r"(a[mt][1]), "r"(a[mt][2]), "r"(a[mt][3]),
                          "r"(b[nn][0]), "r"(b[nn][1]));
        }
    }

    // epilogue
#pragma unroll
    for (int mt = 0; mt < 4; mt++) {
        int row = m0 + wm + mt * 16 + (lane >> 2);
#pragma unroll
        for (int nn = 0; nn < 8; nn++) {
            int col = n0 + wn + nn * 8 + (lane & 3) * 2;
            if (EPI == EPI_T32_LK) {
                float b0 = bias[col], b1 = bias[col + 1];
                float v0 = acc[mt][nn][0] + b0, v1 = acc[mt][nn][1] + b1;
                float v2 = acc[mt][nn][2] + b0, v3 = acc[mt][nn][3] + b1;
                v0 = (v0 > 0.f) ? v0 : 0.01f * v0;
                v1 = (v1 > 0.f) ? v1 : 0.01f * v1;
                v2 = (v2 > 0.f) ? v2 : 0.01f * v2;
                v3 = (v3 > 0.f) ? v3 : 0.01f * v3;
                size_t r0 = (size_t)row * Npad, r1 = (size_t)(row + 8) * Npad;
                Ct[r0 + permcol(col)] = tf32u(v0);
                Ct[r0 + permcol(col + 1)] = tf32u(v1);
                Ct[r1 + permcol(col)] = tf32u(v2);
                Ct[r1 + permcol(col + 1)] = tf32u(v3);
            } else if (EPI == EPI_MEANLV) {
                float b0 = g_mlvb[col], b1 = g_mlvb[col + 1];
                float v0 = acc[mt][nn][0] + b0, v1 = acc[mt][nn][1] + b1;
                float v2 = acc[mt][nn][2] + b0, v3 = acc[mt][nn][3] + b1;
                float* d0 = (col < 64) ? C0 : C1;
                int cc = (col < 64) ? col : col - 64;
                d0[(size_t)row * 64 + cc] = v0;
                d0[(size_t)row * 64 + cc + 1] = v1;
                d0[(size_t)(row + 8) * 64 + cc] = v2;
                d0[(size_t)(row + 8) * 64 + cc + 1] = v3;
            } else {
                if (col + 1 < N) {
                    float b0 = bias[col], b1 = bias[col + 1];
                    float v0 = acc[mt][nn][0] + b0, v1 = acc[mt][nn][1] + b1;
                    float v2 = acc[mt][nn][2] + b0, v3 = acc[mt][nn][3] + b1;
                    if (EPI == EPI_F32_SIG) {
                        v0 = 1.f / (1.f + __expf(-v0));
                        v1 = 1.f / (1.f + __expf(-v1));
                        v2 = 1.f / (1.f + __expf(-v2));
                        v3 = 1.f / (1.f + __expf(-v3));
                    }
                    float2 p0; p0.x = v0; p0.y = v1;
                    float2 p1; p1.x = v2; p1.y = v3;
                    *(float2*)&C0[(size_t)row * N + col] = p0;
                    *(float2*)&C0[(size_t)(row + 8) * N + col] = p1;
                } else if (col < N) {
                    float b0 = bias[col];
                    float v0 = acc[mt][nn][0] + b0, v2 = acc[mt][nn][2] + b0;
                    if (EPI == EPI_F32_SIG) {
                        v0 = 1.f / (1.f + __expf(-v0));
                        v2 = 1.f / (1.f + __expf(-v2));
                    }
                    C0[(size_t)row * N + col] = v0;
                    C0[(size_t)(row + 8) * N + col] = v2;
                }
            }
        }
    }
}

// ---------------------------------------------------------------------------
// converters (B fmt: pair (k, k+4) -> adjacent words, uint2 writes)
// ---------------------------------------------------------------------------
__global__ void conv_B_kernel(const float* __restrict__ W, uint32_t* __restrict__ Wt,
                              int K, int N, int Kpad, int Npad)
{
    size_t i = (size_t)blockIdx.x * 256 + threadIdx.x;   // (Kpad/2)*Npad
    if (i >= (size_t)(Kpad / 2) * Npad) return;
    int pg = (int)(i / Npad), n = (int)(i - (size_t)pg * Npad);
    int g = pg >> 2, qq = pg & 3;
    int k0 = g * 8 + qq, k1 = k0 + 4;
    float v0 = (k0 < K && n < N) ? W[(size_t)k0 * N + n] : 0.f;
    float v1 = (k1 < K && n < N) ? W[(size_t)k1 * N + n] : 0.f;
    uint2 o; o.x = tf32u(v0); o.y = tf32u(v1);
    *(uint2*)&Wt[i * 2] = o;
}

__global__ void conv_mlv_kernel(const float* __restrict__ mw, const float* __restrict__ lw,
                                const float* __restrict__ mb, const float* __restrict__ lb)
{
    int i = blockIdx.x * 256 + threadIdx.x;   // (Hdim/2)*128
    if (i >= (Hdim / 2) * 128) return;
    int pg = i >> 7, n = i & 127;
    int g = pg >> 2, qq = pg & 3;
    int k0 = g * 8 + qq, k1 = k0 + 4;
    float v0 = (n < 64) ? mw[k0 * 64 + n] : lw[k0 * 64 + n - 64];
    float v1 = (n < 64) ? mw[k1 * 64 + n] : lw[k1 * 64 + n - 64];
    uint2 o; o.x = tf32u(v0); o.y = tf32u(v1);
    *(uint2*)&g_mlvt[(size_t)i * 2] = o;
    if (pg == 0) g_mlvb[n] = (n < 64) ? mb[n] : lb[n - 64];
}

__global__ void conv_x_kernel(const float* __restrict__ x, uint32_t* __restrict__ xt)
{
    int g = blockIdx.x * 256 + threadIdx.x;   // Bsz * DGRP groups of 8
    if (g >= Bsz * DGRP) return;
    int m = g / DGRP, gi = g - m * DGRP;
    int k = gi * 8;
    float in[8];
    if (k + 8 <= Ddim) {
        const float* p = x + (size_t)m * Ddim + k;
        float4 v0 = *(const float4*)p;
        float4 v1 = *(const float4*)(p + 4);
        in[0] = v0.x; in[1] = v0.y; in[2] = v0.z; in[3] = v0.w;
        in[4] = v1.x; in[5] = v1.y; in[6] = v1.z; in[7] = v1.w;
    } else {
#pragma unroll
        for (int j = 0; j < 8; j++)
            in[j] = (k + j < Ddim) ? x[(size_t)m * Ddim + k + j] : 0.f;
    }
    uint4 o0, o1;   // A fmt perm: 0,2,4,6,1,3,5,7
    o0.x = tf32u(in[0]); o0.z = tf32u(in[1]);
    o1.x = tf32u(in[2]); o1.z = tf32u(in[3]);
    o0.y = tf32u(in[4]); o0.w = tf32u(in[5]);
    o1.y = tf32u(in[6]); o1.w = tf32u(in[7]);
    uint32_t* d = xt + (size_t)m * KPAD_D + k;
    *(uint4*)d = o0;
    *(uint4*)(d + 4) = o1;
}

// ---------------------------------------------------------------------------
// BatchNorm stats + apply(-> tf32 A fmt)
// ---------------------------------------------------------------------------
__global__ void bn_stats_kernel(const float* __restrict__ h,
                                const float* __restrict__ gamma,
                                const float* __restrict__ beta)
{
    const int col = blockIdx.x * 32 + (threadIdx.x & 31);
    const int rg = threadIdx.x >> 5;
    float s = 0.f, s2 = 0.f;
    for (int r = rg; r < Bsz; r += 8) {
        float v = h[(size_t)r * Hdim + col];
        s += v; s2 += v * v;
    }
    __shared__ float ss[8][33], sq[8][33];
    ss[rg][threadIdx.x & 31] = s;
    sq[rg][threadIdx.x & 31] = s2;
    __syncthreads();
    if (rg == 0) {
        int c = threadIdx.x & 31;
        float S = 0.f, S2 = 0.f;
#pragma unroll
        for (int i = 0; i < 8; i++) { S += ss[i][c]; S2 += sq[i][c]; }
        float mean = S * (1.f / Bsz);
        float var = S2 * (1.f / Bsz) - mean * mean;
        float rstd = 1.f / sqrtf(var + 1e-5f);
        float sc = gamma[col] * rstd;
        g_scale[col] = sc;
        g_shift[col] = beta[col] - mean * sc;
    }
}

__global__ void bn_apply_kernel(const float* __restrict__ h, uint32_t* __restrict__ hnt)
{
    int i = blockIdx.x * blockDim.x + threadIdx.x;
    int col = i & (Hdim - 1);
    float v = fmaf(h[i], g_scale[col], g_shift[col]);
    v = fmaxf(v, 0.f);
    hnt[(i & ~(Hdim - 1)) | permcol(col)] = tf32u(v);
}

// ---------------------------------------------------------------------------
// gumbel + 50-step continuous_topk + xm (tf32 A fmt), packed f32x2
// ---------------------------------------------------------------------------
#define TPB 256
#define EPT 20
#define NP  10

typedef unsigned long long u64t;
#define MUL2(o,a,b)   asm("mul.rn.f32x2 %0,%1,%2;"    : "=l"(o) : "l"(a), "l"(b))
#define ADD2(o,a,b)   asm("add.rn.f32x2 %0,%1,%2;"    : "=l"(o) : "l"(a), "l"(b))
#define FMA2(o,a,b,c) asm("fma.rn.f32x2 %0,%1,%2,%3;" : "=l"(o) : "l"(a), "l"(b), "l"(c))
#define PACK2(o,lo,hi)   asm("mov.b64 %0,{%1,%2};" : "=l"(o) : "f"(lo), "f"(hi))
#define UNPACK2(lo,hi,i) asm("mov.b64 {%0,%1},%2;" : "=f"(lo), "=f"(hi) : "l"(i))

__device__ __forceinline__ float warp_sum(float v) {
#pragma unroll
    for (int o = 16; o; o >>= 1) v += __shfl_xor_sync(0xffffffffu, v, o);
    return v;
}
__device__ __forceinline__ float warp_max(float v) {
#pragma unroll
    for (int o = 16; o; o >>= 1) v = fmaxf(v, __shfl_xor_sync(0xffffffffu, v, o));
    return v;
}

__global__ __launch_bounds__(TPB) void topk_kernel(
    const float* __restrict__ w, const float* __restrict__ noise_u,
    const float* __restrict__ x, uint32_t* __restrict__ xmt)
{
    __shared__ float sred[2][8];
    const int row = blockIdx.x;
    const int tid = threadIdx.x;
    const int lane = tid & 31;
    const int wid = tid >> 5;

    const float* wr = w + (size_t)row * Ddim;
    const float* ur = noise_u + (size_t)row * Ddim;
    const float* xr = x + (size_t)row * Ddim;

    float ev[EPT];
    float mymax = -INFINITY;
#pragma unroll
    for (int i = 0; i < EPT; i++) {
        int idx = tid + i * TPB;
        float v;
        if (idx < Ddim) {
            float u = ur[idx] + 1e-30f;
            v = wr[idx] + logf(-logf(u));
        } else v = -INFINITY;
        ev[i] = v;
        mymax = fmaxf(mymax, v);
    }
    mymax = warp_max(mymax);
    if (lane == 0) sred[0][wid] = mymax;
    __syncthreads();
    float bmax = sred[0][0];
#pragma unroll
    for (int i = 1; i < 8; i++) bmax = fmaxf(bmax, sred[0][i]);
    __syncthreads();

    u64t e2[NP], kh2[NP], ONE2, NEG2;
    PACK2(ONE2, 1.0f, 1.0f);
    PACK2(NEG2, -1.0f, -1.0f);
#pragma unroll
    for (int i = 0; i < NP; i++) {
        float a0 = (tid + (2 * i) * TPB < Ddim) ? __expf((ev[2 * i] - bmax) * 10.0f) : 0.f;
        float a1 = (tid + (2 * i + 1) * TPB < Ddim) ? __expf((ev[2 * i + 1] - bmax) * 10.0f) : 0.f;
        PACK2(e2[i], a0, a1);
        PACK2(kh2[i], 0.f, 0.f);
    }

    for (int step = 0; step < 50; step++) {
        u64t acc0 = e2[0], acc1 = e2[1];
#pragma unroll
        for (int i = 2; i < NP; i += 2) {
            ADD2(acc0, acc0, e2[i]);
            ADD2(acc1, acc1, e2[i + 1]);
        }
        ADD2(acc0, acc0, acc1);
        float slo, shi;
        UNPACK2(slo, shi, acc0);
        float s = warp_sum(slo + shi);
        if (lane == 0) sred[step & 1][wid] = s;
        __syncthreads();
        float tot = 0.f;
#pragma unroll
        for (int i = 0; i < 8; i++) tot += sred[step & 1][i];
        float r = 1.0f / fmaxf(tot, 1e-35f);
        u64t rr; PACK2(rr, r, r);
#pragma unroll
        for (int i = 0; i < NP; i++) {
            u64t o, m, m2, m4, m8, m10;
            MUL2(o, e2[i], rr);
            ADD2(kh2[i], kh2[i], o);
            FMA2(m, o, NEG2, ONE2);      // m = 1 - o
            MUL2(m2, m, m);
            MUL2(m4, m2, m2);
            MUL2(m8, m4, m4);
            MUL2(m10, m8, m2);
            MUL2(e2[i], e2[i], m10);     // e *= m^10 == exp((w + log m)/T)
        }
    }

    uint32_t* xo = xmt + (size_t)row * KPAD_D;
#pragma unroll
    for (int i = 0; i < NP; i++) {
        float k0, k1;
        UNPACK2(k0, k1, kh2[i]);
        int i0 = tid + (2 * i) * TPB;
        int i1 = tid + (2 * i + 1) * TPB;
        if (i0 < Ddim) xo[permcol(i0)] = tf32u(xr[i0] * k0);
        if (i1 < Ddim) xo[permcol(i1)] = tf32u(xr[i1] * k1);
    }
}

// ---------------------------------------------------------------------------
// z = mu + eps*exp(0.5*logvar)  -> tf32 A fmt
// ---------------------------------------------------------------------------
__global__ void reparam_kernel(const float* __restrict__ mu,
                               const float* __restrict__ lv,
                               const float* __restrict__ eps,
                               uint32_t* __restrict__ zt)
{
    int i = blockIdx.x * blockDim.x + threadIdx.x;
    int col = i & 63;
    float zv = fmaf(eps[i], expf(0.5f * lv[i]), mu[i]);
    zt[(i & ~63) | permcol(col)] = tf32u(zv);
}

// ---------------------------------------------------------------------------
// host launch helpers
// ---------------------------------------------------------------------------
template <int EPI>
static void gemm(const uint32_t* At, const uint32_t* Bt, const float* bias,
                 float* C0, float* C1, uint32_t* Ct, int M, int N, int Kpad, int Npad)
{
    static bool done = false;
    if (!done) {
        cudaFuncSetAttribute(tc2_gemm<EPI>,
                             cudaFuncAttributeMaxDynamicSharedMemorySize, GEMM_SMEM);
        done = true;
    }
    dim3 g(Npad / 128, M / 128), b(128);
    tc2_gemm<EPI><<<g, b, GEMM_SMEM>>>(At, Bt, bias, C0, C1, Ct, M, N, Kpad, Npad);
}

static inline int cdiv(int a, int b) { return (a + b - 1) / b; }
static inline int cdivz(size_t a, int b) { return (int)((a + b - 1) / b); }

extern "C" void kernel_launch(void* const* d_in, const int* in_sizes, int n_in,
                              void* d_out, int out_size)
{
    const float* x       = (const float*)d_in[0];
    const float* noise_u = (const float*)d_in[1];
    const float* eps     = (const float*)d_in[2];
    const float* wc_w1   = (const float*)d_in[3];
    const float* wc_b1   = (const float*)d_in[4];
    const float* bn_g    = (const float*)d_in[5];
    const float* bn_b    = (const float*)d_in[6];
    const float* wc_w2   = (const float*)d_in[7];
    const float* wc_b2   = (const float*)d_in[8];
    const float* enc_w1  = (const float*)d_in[9];
    const float* enc_b1  = (const float*)d_in[10];
    const float* enc_w2  = (const float*)d_in[11];
    const float* enc_b2  = (const float*)d_in[12];
    const float* enc_w3  = (const float*)d_in[13];
    const float* enc_b3  = (const float*)d_in[14];
    const float* enc_w4  = (const float*)d_in[15];
    const float* enc_b4  = (const float*)d_in[16];
    const float* mean_w  = (const float*)d_in[17];
    const float* mean_b  = (const float*)d_in[18];
    const float* lv_w    = (const float*)d_in[19];
    const float* lv_b    = (const float*)d_in[20];
    const float* dec_w1  = (const float*)d_in[21];
    const float* dec_b1  = (const float*)d_in[22];
    const float* dec_w2  = (const float*)d_in[23];
    const float* dec_b2  = (const float*)d_in[24];

    float *h_, *w_;
    uint32_t *xt_, *xmt_, *hnt_, *e1t_, *e2t_, *e3t_, *e4t_, *zt_;
    uint32_t *w1t_, *w2t_, *ew1t_, *ew2t_, *ew3t_, *ew4t_, *mlvt_, *dw1t_, *dw2t_;
    cudaGetSymbolAddress((void**)&h_, g_h);
    cudaGetSymbolAddress((void**)&w_, g_w);
    cudaGetSymbolAddress((void**)&xt_, g_xt);
    cudaGetSymbolAddress((void**)&xmt_, g_xmt);
    cudaGetSymbolAddress((void**)&hnt_, g_hnt);
    cudaGetSymbolAddress((void**)&e1t_, g_e1t);
    cudaGetSymbolAddress((void**)&e2t_, g_e2t);
    cudaGetSymbolAddress((void**)&e3t_, g_e3t);
    cudaGetSymbolAddress((void**)&e4t_, g_e4t);
    cudaGetSymbolAddress((void**)&zt_, g_zt);
    cudaGetSymbolAddress((void**)&w1t_, g_w1t);
    cudaGetSymbolAddress((void**)&w2t_, g_w2t);
    cudaGetSymbolAddress((void**)&ew1t_, g_ew1t);
    cudaGetSymbolAddress((void**)&ew2t_, g_ew2t);
    cudaGetSymbolAddress((void**)&ew3t_, g_ew3t);
    cudaGetSymbolAddress((void**)&ew4t_, g_ew4t);
    cudaGetSymbolAddress((void**)&mlvt_, g_mlvt);
    cudaGetSymbolAddress((void**)&dw1t_, g_dw1t);
    cudaGetSymbolAddress((void**)&dw2t_, g_dw2t);

    float* out = (float*)d_out;
    const size_t OFF_MU = (size_t)Bsz * Ddim;
    const size_t OFF_LV = OFF_MU + (size_t)Bsz * Zdim;
    float* mu_out = out + OFF_MU;
    float* lv_out = out + OFF_LV;

    // ---- weight + input conversions (B fmt paired; A fmt for x) ----
    conv_B_kernel<<<cdivz((size_t)(KPAD_D / 2) * Hdim, 256), 256>>>(wc_w1, w1t_, Ddim, Hdim, KPAD_D, Hdim);
    conv_B_kernel<<<cdivz((size_t)(Hdim / 2) * NPAD_D, 256), 256>>>(wc_w2, w2t_, Hdim, Ddim, Hdim, NPAD_D);
    conv_B_kernel<<<cdivz((size_t)(KPAD_D / 2) * 2 * Hdim, 256), 256>>>(enc_w1, ew1t_, Ddim, 2 * Hdim, KPAD_D, 2 * Hdim);
    conv_B_kernel<<<cdivz((size_t)Hdim * Hdim, 256), 256>>>(enc_w2, ew2t_, 2 * Hdim, Hdim, 2 * Hdim, Hdim);
    conv_B_kernel<<<cdivz((size_t)(Hdim / 2) * Hdim, 256), 256>>>(enc_w3, ew3t_, Hdim, Hdim, Hdim, Hdim);
    conv_B_kernel<<<cdivz((size_t)(Hdim / 2) * Hdim, 256), 256>>>(enc_w4, ew4t_, Hdim, Hdim, Hdim, Hdim);
    conv_mlv_kernel<<<cdiv((Hdim / 2) * 128, 256), 256>>>(mean_w, lv_w, mean_b, lv_b);
    conv_B_kernel<<<cdivz((size_t)(Zdim / 2) * 2 * Hdim, 256), 256>>>(dec_w1, dw1t_, Zdim, 2 * Hdim, Zdim, 2 * Hdim);
    conv_B_kernel<<<cdivz((size_t)Hdim * NPAD_D, 256), 256>>>(dec_w2, dw2t_, 2 * Hdim, Ddim, 2 * Hdim, NPAD_D);
    conv_x_kernel<<<cdiv(Bsz * DGRP, 256), 256>>>(x, xt_);

    // 1) h = x @ wc_w1 + b1                       [4096,512] K=5024
    gemm<EPI_F32>(xt_, w1t_, wc_b1, h_, nullptr, nullptr, Bsz, Hdim, KPAD_D, Hdim);

    // 2) batchnorm stats + apply(+relu) -> hn tf32
    bn_stats_kernel<<<Hdim / 32, 256>>>(h_, bn_g, bn_b);
    bn_apply_kernel<<<(Bsz * Hdim) / 256, 256>>>(h_, hnt_);

    // 3) w = hn @ wc_w2 + b2                      [4096,5000] K=512
    gemm<EPI_F32>(hnt_, w2t_, wc_b2, w_, nullptr, nullptr, Bsz, Ddim, Hdim, NPAD_D);

    // 4) gumbel + continuous_topk + xm (tf32)
    topk_kernel<<<Bsz, TPB>>>(w_, noise_u, x, xmt_);

    // 5) encoder (tf32-only outputs)
    gemm<EPI_T32_LK>(xmt_, ew1t_, enc_b1, nullptr, nullptr, e1t_, Bsz, 2 * Hdim, KPAD_D, 2 * Hdim);
    gemm<EPI_T32_LK>(e1t_, ew2t_, enc_b2, nullptr, nullptr, e2t_, Bsz, Hdim, 2 * Hdim, Hdim);
    gemm<EPI_T32_LK>(e2t_, ew3t_, enc_b3, nullptr, nullptr, e3t_, Bsz, Hdim, Hdim, Hdim);
    gemm<EPI_T32_LK>(e3t_, ew4t_, enc_b4, nullptr, nullptr, e4t_, Bsz, Hdim, Hdim, Hdim);

    // mean|logvar merged, N=128 -> d_out tail
    gemm<EPI_MEANLV>(e4t_, mlvt_, nullptr, mu_out, lv_out, nullptr, Bsz, 128, Hdim, 128);

    // 6) reparameterize -> z tf32
    reparam_kernel<<<(Bsz * Zdim) / 256, 256>>>(mu_out, lv_out, eps, zt_);

    // 7) decoder
    gemm<EPI_T32_LK>(zt_, dw1t_, dec_b1, nullptr, nullptr, e1t_, Bsz, 2 * Hdim, Zdim, 2 * Hdim);
    gemm<EPI_F32_SIG>(e1t_, dw2t_, dec_b2, out, nullptr, nullptr, Bsz, Ddim, 2 * Hdim, NPAD_D);
}

// round 16
// speedup vs baseline: 1.1849x; 1.1849x over previous
#include <cuda_runtime.h>
#include <cuda_bf16.h>
#include <math.h>
#include <stdint.h>

// ---------------------------------------------------------------------------
// VAE_Gumbel: B=4096, D=5000, H=512, Z=64
// R16: two GEMM variants sharing one body:
//   BN=128 (2 CTAs/SM) for small-N, BN=256 (1 CTA/SM, higher FLOP/smem-byte)
//   for GEMM3/enc1/dec2. Paired-B ld.v2 fragments everywhere (R15-verified).
//   Launch order arranged so ncu (-s 5 -c 1) profiles GEMM1.
// ---------------------------------------------------------------------------

#define Bsz 4096
#define Ddim 5000
#define Hdim 512
#define Zdim 64
#define KPAD_D 5024
#define NPAD_D 5120
#define DGRP 628             // KPAD_D / 8

__device__ float g_h[Bsz * Hdim];
__device__ float g_w[(size_t)Bsz * Ddim];
__device__ float g_scale[Hdim];
__device__ float g_shift[Hdim];
__device__ float g_mlvb[128];

__device__ uint32_t g_xt[(size_t)Bsz * KPAD_D];   // x,  A fmt (k-paired)
__device__ uint32_t g_xmt[(size_t)Bsz * KPAD_D];  // xm, A fmt
__device__ uint32_t g_hnt[Bsz * Hdim];            // hn, A fmt
__device__ uint32_t g_e1t[Bsz * 2 * Hdim];
__device__ uint32_t g_e2t[Bsz * Hdim];
__device__ uint32_t g_e3t[Bsz * Hdim];
__device__ uint32_t g_e4t[Bsz * Hdim];
__device__ uint32_t g_zt[Bsz * Zdim];
// B fmt: word = pg*2*Npad + 2n + h ; pg=(k>>3)*4+(k&3), h=(k>>2)&1
__device__ uint32_t g_w1t[(size_t)KPAD_D * Hdim];
__device__ uint32_t g_w2t[(size_t)Hdim * NPAD_D];
__device__ uint32_t g_ew1t[(size_t)KPAD_D * 2 * Hdim];
__device__ uint32_t g_ew2t[2 * Hdim * Hdim];
__device__ uint32_t g_ew3t[Hdim * Hdim];
__device__ uint32_t g_ew4t[Hdim * Hdim];
__device__ uint32_t g_mlvt[Hdim * 128];
__device__ uint32_t g_dw1t[Zdim * 2 * Hdim];
__device__ uint32_t g_dw2t[(size_t)2 * Hdim * NPAD_D];

__device__ __forceinline__ unsigned tf32u(float x) {
    unsigned r;
    asm("cvt.rna.tf32.f32 %0, %1;" : "=r"(r) : "f"(x));
    return r;
}
__device__ __forceinline__ uint32_t smem_u32(const void* p) {
    uint32_t a;
    asm("{ .reg .u64 t; cvta.to.shared.u64 t, %1; cvt.u32.u64 %0, t; }"
        : "=r"(a) : "l"(p));
    return a;
}
__device__ __forceinline__ int permcol(int c) {
    return (c & ~7) | ((c & 3) * 2) | ((c >> 2) & 1);
}
__device__ __forceinline__ void cp_async16(uint32_t dst, const uint32_t* src) {
    asm volatile("cp.async.cg.shared.global [%0], [%1], 16;\n"
                 :: "r"(dst), "l"(src));
}

#define EPI_F32      0
#define EPI_F32_SIG  1
#define EPI_T32_LK   2
#define EPI_MEANLV   3

#define A_STAGE 16384   // 128 rows * 128B

// ---------------------------------------------------------------------------
// shared GEMM body. At: [M][Kpad] A fmt. Bt: B fmt paired.
// CTA tile 128xBN, BK=32, 3-stage cp.async, 256 thr = 8 warps (2m x 4n),
// warp tile 64x(BN/4). Kpad%32==0, Npad%BN==0, M%128==0.
// ---------------------------------------------------------------------------
template <int EPI, int BN>
__device__ __forceinline__ void gemm_body(
    const uint32_t* __restrict__ At, const uint32_t* __restrict__ Bt,
    const float* __restrict__ bias,
    float* __restrict__ C0, float* __restrict__ C1, uint32_t* __restrict__ Ct,
    int M, int N, int Kpad, int Npad)
{
    constexpr int NN = BN / 32;                  // nn tiles per warp (4 or 8)
    constexpr int B_STAGE = BN * 128;            // 16 pair-rows * BN*8 B
    constexpr int STAGE = A_STAGE + B_STAGE;

    extern __shared__ char smem[];
    const uint32_t sbase = smem_u32(smem);
    const int tid = threadIdx.x;
    const int lane = tid & 31;
    const int wid = tid >> 5;
    const int wm = (wid & 1) * 64;
    const int wn = (wid >> 1) * (BN / 4);
    const int m0 = blockIdx.y * 128;
    const int n0 = blockIdx.x * BN;

    float acc[4][NN][4];
#pragma unroll
    for (int i = 0; i < 4; i++)
#pragma unroll
        for (int j = 0; j < NN; j++)
#pragma unroll
            for (int q = 0; q < 4; q++) acc[i][j][q] = 0.f;

    const int nt = Kpad >> 5;

    // stage loader (verified layouts: A = R14, B = R15 paired, parameterized)
    const int am = tid >> 1, ahf = tid & 1;
    const int asw = (am & 3) << 1;
    const int bpr = tid >> 4, bcc = tid & 15;
    const uint32_t bsw = (bpr & 3) * 32;

    auto stage_load = [&](int slot, int k0) {
        const uint32_t sb = sbase + slot * STAGE;
        const uint32_t* asrc = At + (size_t)(m0 + am) * Kpad + k0;
        const uint32_t adst = sb + am * 128;
#pragma unroll
        for (int j = 0; j < 4; j++) {
            int c = ahf * 4 + j;
            cp_async16(adst + ((c ^ asw) << 4), asrc + c * 4);
        }
        const uint32_t* bsrc = Bt + ((size_t)(k0 >> 1) + bpr) * (2 * (size_t)Npad)
                                  + 2 * n0 + bcc * 4;
        const uint32_t bdst = sb + A_STAGE + bpr * (BN * 8);
#pragma unroll
        for (int j = 0; j < BN / 32; j++)
            cp_async16(bdst + (((uint32_t)(bcc * 16 + j * 256)) ^ bsw), bsrc + j * 64);
    };

#pragma unroll
    for (int t = 0; t < 2; t++) {
        if (t < nt) stage_load(t, t << 5);
        asm volatile("cp.async.commit_group;\n" ::: "memory");
    }

    const int ar = lane >> 2, q = lane & 3;

    for (int t = 0; t < nt; t++) {
        asm volatile("cp.async.wait_group 1;\n" ::: "memory");
        __syncthreads();

        if (t + 2 < nt) stage_load((t + 2) % 3, (t + 2) << 5);
        asm volatile("cp.async.commit_group;\n" ::: "memory");

        const uint32_t as = sbase + (t % 3) * STAGE;
        const uint32_t bs = as + A_STAGE;

#pragma unroll
        for (int kk = 0; kk < 4; kk++) {
            uint32_t a[4][4], b[NN][2];
#pragma unroll
            for (int mt = 0; mt < 4; mt++) {
                int m = wm + mt * 16 + ar;
                uint32_t ad0 = as + m * 128 +
                    (((kk * 2 + (q >> 1)) ^ ((m & 3) << 1)) << 4) + (q & 1) * 8;
                asm("ld.shared.v2.u32 {%0,%1},[%2];"
                    : "=r"(a[mt][0]), "=r"(a[mt][2]) : "r"(ad0));
                int m1 = m + 8;
                uint32_t ad1 = as + m1 * 128 +
                    (((kk * 2 + (q >> 1)) ^ ((m1 & 3) << 1)) << 4) + (q & 1) * 8;
                asm("ld.shared.v2.u32 {%0,%1},[%2];"
                    : "=r"(a[mt][1]), "=r"(a[mt][3]) : "r"(ad1));
            }
            const uint32_t brow = bs + (kk * 4 + q) * (BN * 8);
            const uint32_t bxor = q * 32;
#pragma unroll
            for (int nn = 0; nn < NN; nn++) {
                int n = wn + nn * 8 + ar;
                asm("ld.shared.v2.u32 {%0,%1},[%2];"
                    : "=r"(b[nn][0]), "=r"(b[nn][1])
                    : "r"(brow + ((uint32_t)(n * 8) ^ bxor)));
            }
#pragma unroll
            for (int mt = 0; mt < 4; mt++)
#pragma unroll
                for (int nn = 0; nn < NN; nn++)
                    asm volatile(
                        "mma.sync.aligned.m16n8k8.row.col.f32.tf32.tf32.f32 "
                        "{%0,%1,%2,%3},{%4,%5,%6,%7},{%8,%9},{%0,%1,%2,%3};\n"
                        : "+f"(acc[mt][nn][0]), "+f"(acc[mt][nn][1]),
                          "+f"(acc[mt][nn][2]), "+f"(acc[mt][nn][3])
                        : "r"(a[mt][0]), "r"(a[mt][1]), "r"(a[mt][2]), "r"(a[mt][3]),
                          "r"(b[nn][0]), "r"(b[nn][1]));
        }
    }

    // epilogue
#pragma unroll
    for (int mt = 0; mt < 4; mt++) {
        int row = m0 + wm + mt * 16 + (lane >> 2);
#pragma unroll
        for (int nn = 0; nn < NN; nn++) {
            int col = n0 + wn + nn * 8 + (lane & 3) * 2;
            if (EPI == EPI_T32_LK) {
                float b0 = bias[col], b1 = bias[col + 1];
                float v0 = acc[mt][nn][0] + b0, v1 = acc[mt][nn][1] + b1;
                float v2 = acc[mt][nn][2] + b0, v3 = acc[mt][nn][3] + b1;
                v0 = (v0 > 0.f) ? v0 : 0.01f * v0;
                v1 = (v1 > 0.f) ? v1 : 0.01f * v1;
                v2 = (v2 > 0.f) ? v2 : 0.01f * v2;
                v3 = (v3 > 0.f) ? v3 : 0.01f * v3;
                size_t r0 = (size_t)row * Npad, r1 = (size_t)(row + 8) * Npad;
                Ct[r0 + permcol(col)] = tf32u(v0);
                Ct[r0 + permcol(col + 1)] = tf32u(v1);
                Ct[r1 + permcol(col)] = tf32u(v2);
                Ct[r1 + permcol(col + 1)] = tf32u(v3);
            } else if (EPI == EPI_MEANLV) {
                float b0 = g_mlvb[col], b1 = g_mlvb[col + 1];
                float v0 = acc[mt][nn][0] + b0, v1 = acc[mt][nn][1] + b1;
                float v2 = acc[mt][nn][2] + b0, v3 = acc[mt][nn][3] + b1;
                float* d0 = (col < 64) ? C0 : C1;
                int cc = (col < 64) ? col : col - 64;
                d0[(size_t)row * 64 + cc] = v0;
                d0[(size_t)row * 64 + cc + 1] = v1;
                d0[(size_t)(row + 8) * 64 + cc] = v2;
                d0[(size_t)(row + 8) * 64 + cc + 1] = v3;
            } else {
                if (col + 1 < N) {
                    float b0 = bias[col], b1 = bias[col + 1];
                    float v0 = acc[mt][nn][0] + b0, v1 = acc[mt][nn][1] + b1;
                    float v2 = acc[mt][nn][2] + b0, v3 = acc[mt][nn][3] + b1;
                    if (EPI == EPI_F32_SIG) {
                        v0 = 1.f / (1.f + __expf(-v0));
                        v1 = 1.f / (1.f + __expf(-v1));
                        v2 = 1.f / (1.f + __expf(-v2));
                        v3 = 1.f / (1.f + __expf(-v3));
                    }
                    float2 p0; p0.x = v0; p0.y = v1;
                    float2 p1; p1.x = v2; p1.y = v3;
                    *(float2*)&C0[(size_t)row * N + col] = p0;
                    *(float2*)&C0[(size_t)(row + 8) * N + col] = p1;
                } else if (col < N) {
                    float b0 = bias[col];
                    float v0 = acc[mt][nn][0] + b0, v2 = acc[mt][nn][2] + b0;
                    if (EPI == EPI_F32_SIG) {
                        v0 = 1.f / (1.f + __expf(-v0));
                        v2 = 1.f / (1.f + __expf(-v2));
                    }
                    C0[(size_t)row * N + col] = v0;
                    C0[(size_t)(row + 8) * N + col] = v2;
                }
            }
        }
    }
}

template <int EPI>
__global__ __launch_bounds__(256, 2) void tcg128(
    const uint32_t* __restrict__ At, const uint32_t* __restrict__ Bt,
    const float* __restrict__ bias, float* __restrict__ C0,
    float* __restrict__ C1, uint32_t* __restrict__ Ct,
    int M, int N, int Kpad, int Npad)
{
    gemm_body<EPI, 128>(At, Bt, bias, C0, C1, Ct, M, N, Kpad, Npad);
}

template <int EPI>
__global__ __launch_bounds__(256, 1) void tcg256(
    const uint32_t* __restrict__ At, const uint32_t* __restrict__ Bt,
    const float* __restrict__ bias, float* __restrict__ C0,
    float* __restrict__ C1, uint32_t* __restrict__ Ct,
    int M, int N, int Kpad, int Npad)
{
    gemm_body<EPI, 256>(At, Bt, bias, C0, C1, Ct, M, N, Kpad, Npad);
}

#define SMEM128 (3 * (A_STAGE + 128 * 128))   // 98304
#define SMEM256 (3 * (A_STAGE + 256 * 128))   // 147456

// ---------------------------------------------------------------------------
// converters (unchanged from R14/R15-verified)
// ---------------------------------------------------------------------------
__global__ void conv_B_kernel(const float* __restrict__ W, uint32_t* __restrict__ Wt,
                              int K, int N, int Kpad, int Npad)
{
    size_t i = (size_t)blockIdx.x * 256 + threadIdx.x;
    if (i >= (size_t)(Kpad / 2) * Npad) return;
    int pg = (int)(i / Npad), n = (int)(i - (size_t)pg * Npad);
    int g = pg >> 2, qq = pg & 3;
    int k0 = g * 8 + qq, k1 = k0 + 4;
    float v0 = (k0 < K && n < N) ? W[(size_t)k0 * N + n] : 0.f;
    float v1 = (k1 < K && n < N) ? W[(size_t)k1 * N + n] : 0.f;
    uint2 o; o.x = tf32u(v0); o.y = tf32u(v1);
    *(uint2*)&Wt[i * 2] = o;
}

__global__ void conv_mlv_kernel(const float* __restrict__ mw, const float* __restrict__ lw,
                                const float* __restrict__ mb, const float* __restrict__ lb)
{
    int i = blockIdx.x * 256 + threadIdx.x;
    if (i >= (Hdim / 2) * 128) return;
    int pg = i >> 7, n = i & 127;
    int g = pg >> 2, qq = pg & 3;
    int k0 = g * 8 + qq, k1 = k0 + 4;
    float v0 = (n < 64) ? mw[k0 * 64 + n] : lw[k0 * 64 + n - 64];
    float v1 = (n < 64) ? mw[k1 * 64 + n] : lw[k1 * 64 + n - 64];
    uint2 o; o.x = tf32u(v0); o.y = tf32u(v1);
    *(uint2*)&g_mlvt[(size_t)i * 2] = o;
    if (pg == 0) g_mlvb[n] = (n < 64) ? mb[n] : lb[n - 64];
}

__global__ void conv_x_kernel(const float* __restrict__ x, uint32_t* __restrict__ xt)
{
    int g = blockIdx.x * 256 + threadIdx.x;
    if (g >= Bsz * DGRP) return;
    int m = g / DGRP, gi = g - m * DGRP;
    int k = gi * 8;
    float in[8];
    if (k + 8 <= Ddim) {
        const float* p = x + (size_t)m * Ddim + k;
        float4 v0 = *(const float4*)p;
        float4 v1 = *(const float4*)(p + 4);
        in[0] = v0.x; in[1] = v0.y; in[2] = v0.z; in[3] = v0.w;
        in[4] = v1.x; in[5] = v1.y; in[6] = v1.z; in[7] = v1.w;
    } else {
#pragma unroll
        for (int j = 0; j < 8; j++)
            in[j] = (k + j < Ddim) ? x[(size_t)m * Ddim + k + j] : 0.f;
    }
    uint4 o0, o1;
    o0.x = tf32u(in[0]); o0.z = tf32u(in[1]);
    o1.x = tf32u(in[2]); o1.z = tf32u(in[3]);
    o0.y = tf32u(in[4]); o0.w = tf32u(in[5]);
    o1.y = tf32u(in[6]); o1.w = tf32u(in[7]);
    uint32_t* d = xt + (size_t)m * KPAD_D + k;
    *(uint4*)d = o0;
    *(uint4*)(d + 4) = o1;
}

// ---------------------------------------------------------------------------
// BatchNorm stats + apply (unchanged)
// ---------------------------------------------------------------------------
__global__ void bn_stats_kernel(const float* __restrict__ h,
                                const float* __restrict__ gamma,
                                const float* __restrict__ beta)
{
    const int col = blockIdx.x * 32 + (threadIdx.x & 31);
    const int rg = threadIdx.x >> 5;
    float s = 0.f, s2 = 0.f;
    for (int r = rg; r < Bsz; r += 8) {
        float v = h[(size_t)r * Hdim + col];
        s += v; s2 += v * v;
    }
    __shared__ float ss[8][33], sq[8][33];
    ss[rg][threadIdx.x & 31] = s;
    sq[rg][threadIdx.x & 31] = s2;
    __syncthreads();
    if (rg == 0) {
        int c = threadIdx.x & 31;
        float S = 0.f, S2 = 0.f;
#pragma unroll
        for (int i = 0; i < 8; i++) { S += ss[i][c]; S2 += sq[i][c]; }
        float mean = S * (1.f / Bsz);
        float var = S2 * (1.f / Bsz) - mean * mean;
        float rstd = 1.f / sqrtf(var + 1e-5f);
        float sc = gamma[col] * rstd;
        g_scale[col] = sc;
        g_shift[col] = beta[col] - mean * sc;
    }
}

__global__ void bn_apply_kernel(const float* __restrict__ h, uint32_t* __restrict__ hnt)
{
    int i = blockIdx.x * blockDim.x + threadIdx.x;
    int col = i & (Hdim - 1);
    float v = fmaf(h[i], g_scale[col], g_shift[col]);
    v = fmaxf(v, 0.f);
    hnt[(i & ~(Hdim - 1)) | permcol(col)] = tf32u(v);
}

// ---------------------------------------------------------------------------
// topk (unchanged from R14 — identical math, identical rel_err)
// ---------------------------------------------------------------------------
#define TPB 256
#define EPT 20
#define NP  10

typedef unsigned long long u64t;
#define MUL2(o,a,b)   asm("mul.rn.f32x2 %0,%1,%2;"    : "=l"(o) : "l"(a), "l"(b))
#define ADD2(o,a,b)   asm("add.rn.f32x2 %0,%1,%2;"    : "=l"(o) : "l"(a), "l"(b))
#define FMA2(o,a,b,c) asm("fma.rn.f32x2 %0,%1,%2,%3;" : "=l"(o) : "l"(a), "l"(b), "l"(c))
#define PACK2(o,lo,hi)   asm("mov.b64 %0,{%1,%2};" : "=l"(o) : "f"(lo), "f"(hi))
#define UNPACK2(lo,hi,i) asm("mov.b64 {%0,%1},%2;" : "=f"(lo), "=f"(hi) : "l"(i))

__device__ __forceinline__ float warp_sum(float v) {
#pragma unroll
    for (int o = 16; o; o >>= 1) v += __shfl_xor_sync(0xffffffffu, v, o);
    return v;
}
__device__ __forceinline__ float warp_max(float v) {
#pragma unroll
    for (int o = 16; o; o >>= 1) v = fmaxf(v, __shfl_xor_sync(0xffffffffu, v, o));
    return v;
}

__global__ __launch_bounds__(TPB) void topk_kernel(
    const float* __restrict__ w, const float* __restrict__ noise_u,
    const float* __restrict__ x, uint32_t* __restrict__ xmt)
{
    __shared__ float sred[2][8];
    const int row = blockIdx.x;
    const int tid = threadIdx.x;
    const int lane = tid & 31;
    const int wid = tid >> 5;

    const float* wr = w + (size_t)row * Ddim;
    const float* ur = noise_u + (size_t)row * Ddim;
    const float* xr = x + (size_t)row * Ddim;

    float ev[EPT];
    float mymax = -INFINITY;
#pragma unroll
    for (int i = 0; i < EPT; i++) {
        int idx = tid + i * TPB;
        float v;
        if (idx < Ddim) {
            float u = ur[idx] + 1e-30f;
            v = wr[idx] + logf(-logf(u));
        } else v = -INFINITY;
        ev[i] = v;
        mymax = fmaxf(mymax, v);
    }
    mymax = warp_max(mymax);
    if (lane == 0) sred[0][wid] = mymax;
    __syncthreads();
    float bmax = sred[0][0];
#pragma unroll
    for (int i = 1; i < 8; i++) bmax = fmaxf(bmax, sred[0][i]);
    __syncthreads();

    u64t e2[NP], kh2[NP], ONE2, NEG2;
    PACK2(ONE2, 1.0f, 1.0f);
    PACK2(NEG2, -1.0f, -1.0f);
#pragma unroll
    for (int i = 0; i < NP; i++) {
        float a0 = (tid + (2 * i) * TPB < Ddim) ? __expf((ev[2 * i] - bmax) * 10.0f) : 0.f;
        float a1 = (tid + (2 * i + 1) * TPB < Ddim) ? __expf((ev[2 * i + 1] - bmax) * 10.0f) : 0.f;
        PACK2(e2[i], a0, a1);
        PACK2(kh2[i], 0.f, 0.f);
    }

    for (int step = 0; step < 50; step++) {
        u64t acc0 = e2[0], acc1 = e2[1];
#pragma unroll
        for (int i = 2; i < NP; i += 2) {
            ADD2(acc0, acc0, e2[i]);
            ADD2(acc1, acc1, e2[i + 1]);
        }
        ADD2(acc0, acc0, acc1);
        float slo, shi;
        UNPACK2(slo, shi, acc0);
        float s = warp_sum(slo + shi);
        if (lane == 0) sred[step & 1][wid] = s;
        __syncthreads();
        float tot = 0.f;
#pragma unroll
        for (int i = 0; i < 8; i++) tot += sred[step & 1][i];
        float r = 1.0f / fmaxf(tot, 1e-35f);
        u64t rr; PACK2(rr, r, r);
#pragma unroll
        for (int i = 0; i < NP; i++) {
            u64t o, m, m2, m4, m8, m10;
            MUL2(o, e2[i], rr);
            ADD2(kh2[i], kh2[i], o);
            FMA2(m, o, NEG2, ONE2);
            MUL2(m2, m, m);
            MUL2(m4, m2, m2);
            MUL2(m8, m4, m4);
            MUL2(m10, m8, m2);
            MUL2(e2[i], e2[i], m10);
        }
    }

    uint32_t* xo = xmt + (size_t)row * KPAD_D;
#pragma unroll
    for (int i = 0; i < NP; i++) {
        float k0, k1;
        UNPACK2(k0, k1, kh2[i]);
        int i0 = tid + (2 * i) * TPB;
        int i1 = tid + (2 * i + 1) * TPB;
        if (i0 < Ddim) xo[permcol(i0)] = tf32u(xr[i0] * k0);
        if (i1 < Ddim) xo[permcol(i1)] = tf32u(xr[i1] * k1);
    }
}

__global__ void reparam_kernel(const float* __restrict__ mu,
                               const float* __restrict__ lv,
                               const float* __restrict__ eps,
                               uint32_t* __restrict__ zt)
{
    int i = blockIdx.x * blockDim.x + threadIdx.x;
    int col = i & 63;
    float zv = fmaf(eps[i], expf(0.5f * lv[i]), mu[i]);
    zt[(i & ~63) | permcol(col)] = tf32u(zv);
}

// ---------------------------------------------------------------------------
// host dispatch
// ---------------------------------------------------------------------------
template <int EPI>
static void gemm128(const uint32_t* At, const uint32_t* Bt, const float* bias,
                    float* C0, float* C1, uint32_t* Ct, int M, int N, int Kpad, int Npad)
{
    static bool done = false;
    if (!done) {
        cudaFuncSetAttribute(tcg128<EPI>,
                             cudaFuncAttributeMaxDynamicSharedMemorySize, SMEM128);
        done = true;
    }
    dim3 g(Npad / 128, M / 128), b(256);
    tcg128<EPI><<<g, b, SMEM128>>>(At, Bt, bias, C0, C1, Ct, M, N, Kpad, Npad);
}

template <int EPI>
static void gemm256(const uint32_t* At, const uint32_t* Bt, const float* bias,
                    float* C0, float* C1, uint32_t* Ct, int M, int N, int Kpad, int Npad)
{
    static bool done = false;
    if (!done) {
        cudaFuncSetAttribute(tcg256<EPI>,
                             cudaFuncAttributeMaxDynamicSharedMemorySize, SMEM256);
        done = true;
    }
    dim3 g(Npad / 256, M / 128), b(256);
    tcg256<EPI><<<g, b, SMEM256>>>(At, Bt, bias, C0, C1, Ct, M, N, Kpad, Npad);
}

static inline int cdiv(int a, int b) { return (a + b - 1) / b; }
static inline int cdivz(size_t a, int b) { return (int)((a + b - 1) / b); }

extern "C" void kernel_launch(void* const* d_in, const int* in_sizes, int n_in,
                              void* d_out, int out_size)
{
    const float* x       = (const float*)d_in[0];
    const float* noise_u = (const float*)d_in[1];
    const float* eps     = (const float*)d_in[2];
    const float* wc_w1   = (const float*)d_in[3];
    const float* wc_b1   = (const float*)d_in[4];
    const float* bn_g    = (const float*)d_in[5];
    const float* bn_b    = (const float*)d_in[6];
    const float* wc_w2   = (const float*)d_in[7];
    const float* wc_b2   = (const float*)d_in[8];
    const float* enc_w1  = (const float*)d_in[9];
    const float* enc_b1  = (const float*)d_in[10];
    const float* enc_w2  = (const float*)d_in[11];
    const float* enc_b2  = (const float*)d_in[12];
    const float* enc_w3  = (const float*)d_in[13];
    const float* enc_b3  = (const float*)d_in[14];
    const float* enc_w4  = (const float*)d_in[15];
    const float* enc_b4  = (const float*)d_in[16];
    const float* mean_w  = (const float*)d_in[17];
    const float* mean_b  = (const float*)d_in[18];
    const float* lv_w    = (const float*)d_in[19];
    const float* lv_b    = (const float*)d_in[20];
    const float* dec_w1  = (const float*)d_in[21];
    const float* dec_b1  = (const float*)d_in[22];
    const float* dec_w2  = (const float*)d_in[23];
    const float* dec_b2  = (const float*)d_in[24];

    float *h_, *w_;
    uint32_t *xt_, *xmt_, *hnt_, *e1t_, *e2t_, *e3t_, *e4t_, *zt_;
    uint32_t *w1t_, *w2t_, *ew1t_, *ew2t_, *ew3t_, *ew4t_, *mlvt_, *dw1t_, *dw2t_;
    cudaGetSymbolAddress((void**)&h_, g_h);
    cudaGetSymbolAddress((void**)&w_, g_w);
    cudaGetSymbolAddress((void**)&xt_, g_xt);
    cudaGetSymbolAddress((void**)&xmt_, g_xmt);
    cudaGetSymbolAddress((void**)&hnt_, g_hnt);
    cudaGetSymbolAddress((void**)&e1t_, g_e1t);
    cudaGetSymbolAddress((void**)&e2t_, g_e2t);
    cudaGetSymbolAddress((void**)&e3t_, g_e3t);
    cudaGetSymbolAddress((void**)&e4t_, g_e4t);
    cudaGetSymbolAddress((void**)&zt_, g_zt);
    cudaGetSymbolAddress((void**)&w1t_, g_w1t);
    cudaGetSymbolAddress((void**)&w2t_, g_w2t);
    cudaGetSymbolAddress((void**)&ew1t_, g_ew1t);
    cudaGetSymbolAddress((void**)&ew2t_, g_ew2t);
    cudaGetSymbolAddress((void**)&ew3t_, g_ew3t);
    cudaGetSymbolAddress((void**)&ew4t_, g_ew4t);
    cudaGetSymbolAddress((void**)&mlvt_, g_mlvt);
    cudaGetSymbolAddress((void**)&dw1t_, g_dw1t);
    cudaGetSymbolAddress((void**)&dw2t_, g_dw2t);

    float* out = (float*)d_out;
    const size_t OFF_MU = (size_t)Bsz * Ddim;
    const size_t OFF_LV = OFF_MU + (size_t)Bsz * Zdim;
    float* mu_out = out + OFF_MU;
    float* lv_out = out + OFF_LV;

    // launches 1-5: exactly the convs GEMM1 needs (+2 fillers) so that
    // launch #6 = GEMM1 lands under ncu's -s 5 -c 1 window.
    conv_x_kernel<<<cdiv(Bsz * DGRP, 256), 256>>>(x, xt_);                       // 1
    conv_B_kernel<<<cdivz((size_t)(KPAD_D / 2) * Hdim, 256), 256>>>(
        wc_w1, w1t_, Ddim, Hdim, KPAD_D, Hdim);                                   // 2
    conv_B_kernel<<<cdivz((size_t)(Hdim / 2) * NPAD_D, 256), 256>>>(
        wc_w2, w2t_, Hdim, Ddim, Hdim, NPAD_D);                                   // 3
    conv_B_kernel<<<cdivz((size_t)(KPAD_D / 2) * 2 * Hdim, 256), 256>>>(
        enc_w1, ew1t_, Ddim, 2 * Hdim, KPAD_D, 2 * Hdim);                         // 4
    conv_mlv_kernel<<<cdiv((Hdim / 2) * 128, 256), 256>>>(mean_w, lv_w, mean_b, lv_b); // 5

    // 1) h = x @ wc_w1 + b1     [4096,512] K=5024     <-- ncu target (#6)
    gemm128<EPI_F32>(xt_, w1t_, wc_b1, h_, nullptr, nullptr, Bsz, Hdim, KPAD_D, Hdim);

    // remaining weight conversions (independent of pipeline position)
    conv_B_kernel<<<cdivz((size_t)Hdim * Hdim, 256), 256>>>(
        enc_w2, ew2t_, 2 * Hdim, Hdim, 2 * Hdim, Hdim);
    conv_B_kernel<<<cdivz((size_t)(Hdim / 2) * Hdim, 256), 256>>>(
        enc_w3, ew3t_, Hdim, Hdim, Hdim, Hdim);
    conv_B_kernel<<<cdivz((size_t)(Hdim / 2) * Hdim, 256), 256>>>(
        enc_w4, ew4t_, Hdim, Hdim, Hdim, Hdim);
    conv_B_kernel<<<cdivz((size_t)(Zdim / 2) * 2 * Hdim, 256), 256>>>(
        dec_w1, dw1t_, Zdim, 2 * Hdim, Zdim, 2 * Hdim);
    conv_B_kernel<<<cdivz((size_t)Hdim * NPAD_D, 256), 256>>>(
        dec_w2, dw2t_, 2 * Hdim, Ddim, 2 * Hdim, NPAD_D);

    // 2) batchnorm stats + apply(+relu) -> hn tf32
    bn_stats_kernel<<<Hdim / 32, 256>>>(h_, bn_g, bn_b);
    bn_apply_kernel<<<(Bsz * Hdim) / 256, 256>>>(h_, hnt_);

    // 3) w = hn @ wc_w2 + b2    [4096,5000] K=512  (BN=256 tile)
    gemm256<EPI_F32>(hnt_, w2t_, wc_b2, w_, nullptr, nullptr, Bsz, Ddim, Hdim, NPAD_D);

    // 4) gumbel + continuous_topk + xm
    topk_kernel<<<Bsz, TPB>>>(w_, noise_u, x, xmt_);

    // 5) encoder
    gemm256<EPI_T32_LK>(xmt_, ew1t_, enc_b1, nullptr, nullptr, e1t_, Bsz, 2 * Hdim, KPAD_D, 2 * Hdim);
    gemm128<EPI_T32_LK>(e1t_, ew2t_, enc_b2, nullptr, nullptr, e2t_, Bsz, Hdim, 2 * Hdim, Hdim);
    gemm128<EPI_T32_LK>(e2t_, ew3t_, enc_b3, nullptr, nullptr, e3t_, Bsz, Hdim, Hdim, Hdim);
    gemm128<EPI_T32_LK>(e3t_, ew4t_, enc_b4, nullptr, nullptr, e4t_, Bsz, Hdim, Hdim, Hdim);

    // mean|logvar merged -> d_out tail
    gemm128<EPI_MEANLV>(e4t_, mlvt_, nullptr, mu_out, lv_out, nullptr, Bsz, 128, Hdim, 128);

    // 6) reparameterize
    reparam_kernel<<<(Bsz * Zdim) / 256, 256>>>(mu_out, lv_out, eps, zt_);

    // 7) decoder
    gemm128<EPI_T32_LK>(zt_, dw1t_, dec_b1, nullptr, nullptr, e1t_, Bsz, 2 * Hdim, Zdim, 2 * Hdim);
    gemm256<EPI_F32_SIG>(e1t_, dw2t_, dec_b2, out, nullptr, nullptr, Bsz, Ddim, 2 * Hdim, NPAD_D);
}